// round 14
// baseline (speedup 1.0000x reference)
#include <cuda_runtime.h>
#include <math.h>
#include <stdint.h>

#define NATOMS_MAX 500000
#define MMOL_MAX   16384
#define DD         256
#define EPS_BN 1e-6f
#define EPS_SM 1e-8f

// ---------------- scratch (static device globals; no allocs) ----------------
__device__ float g_score[NATOMS_MAX];
__device__ float g_pooled[MMOL_MAX * DD];
__device__ float g_ctx[MMOL_MAX * DD];
__device__ float g_gx[MMOL_MAX * 3 * DD];
__device__ float g_gh[MMOL_MAX * 3 * DD];
__device__ float g_sa[MMOL_MAX * DD];      // tf32-rounded superatom (GEMM A only)
__device__ float g_whh_r[3 * DD * DD];     // tf32-rounded gru_whh
__device__ float g_wih_r[3 * DD * DD];     // tf32-rounded gru_wih
__device__ float g_segmax[MMOL_MAX];
__device__ float g_segS[MMOL_MAX];
__device__ float g_sumw[MMOL_MAX];
__device__ int   g_segstart[MMOL_MAX + 1];
__device__ float g_Wa[DD * DD];
__device__ float g_cvec[DD];
__device__ int   g_is32;

__device__ __forceinline__ int load_idx(const void* mi, int i, int is32) {
    if (is32) return ((const int*)mi)[i];
    return (int)((const long long*)mi)[i];
}

__device__ __forceinline__ uint32_t smem_u32(const void* p) {
    uint32_t a;
    asm("{ .reg .u64 t; cvta.to.shared.u64 t, %1; cvt.u32.u64 %0, t; }" : "=r"(a) : "l"(p));
    return a;
}
__device__ __forceinline__ float rna_tf32f(float f) {
    uint32_t u;
    asm("cvt.rna.tf32.f32 %0, %1;" : "=r"(u) : "f"(f));
    return __uint_as_float(u);
}

// ---------------- tiny setup kernels ----------------
__global__ void k_zero_flag() { g_is32 = 0; }

__global__ void k_detect(const void* __restrict__ mi, int n) {
    int i = blockIdx.x * blockDim.x + threadIdx.x;
    if (i >= n) return;
    if ((i & 1) && ((const int*)mi)[i] != 0) atomicOr(&g_is32, 1);
}

__global__ void k_segstart(const void* __restrict__ mi, int n, int Mmol) {
    int i = blockIdx.x * blockDim.x + threadIdx.x;
    if (i >= n) return;
    int is32 = g_is32;
    int cur = load_idx(mi, i, is32);
    if (i == 0) {
        for (int m = 0; m <= cur; m++) g_segstart[m] = 0;
    } else {
        int prev = load_idx(mi, i - 1, is32);
        for (int m = prev + 1; m <= cur; m++) g_segstart[m] = i;
    }
    if (i == n - 1) {
        for (int m = cur + 1; m <= Mmol; m++) g_segstart[m] = n;
    }
}

// round-to-nearest tf32 copy (vectorized)
__global__ void k_round(const float* __restrict__ in, float* __restrict__ out, int n4) {
    int i = blockIdx.x * blockDim.x + threadIdx.x;
    if (i >= n4) return;
    float4 v = ((const float4*)in)[i];
    v.x = rna_tf32f(v.x); v.y = rna_tf32f(v.y);
    v.z = rna_tf32f(v.z); v.w = rna_tf32f(v.w);
    ((float4*)out)[i] = v;
}

__global__ void k_weff(const float* __restrict__ attend_w, const float* __restrict__ attend_b,
                       const float* __restrict__ gamma, const float* __restrict__ beta,
                       const float* __restrict__ mean, const float* __restrict__ var) {
    int i = blockIdx.x * blockDim.x + threadIdx.x;
    if (i >= DD * DD) return;
    int j = i >> 8;
    float g = gamma[j] * rsqrtf(var[j] + EPS_BN);
    g_Wa[i] = rna_tf32f(attend_w[i] * g);
    if ((i & 255) == 0)
        g_cvec[j] = g * (attend_b[j] - mean[j]) + beta[j];
}

// ---------------- fused align-score + online softmax + weighted pooling ----
__global__ void k_pool(const float* __restrict__ superatom, const float* __restrict__ atom,
                       const void* __restrict__ mi, const float* __restrict__ align_w,
                       const float* __restrict__ align_b, int Mmol) {
    int warp = (blockIdx.x * blockDim.x + threadIdx.x) >> 5;
    int lane = threadIdx.x & 31;
    if (warp >= Mmol) return;
    int m = warp;

    float4 ws0 = *(const float4*)(align_w + 4 * lane);
    float4 ws1 = *(const float4*)(align_w + 128 + 4 * lane);
    float4 wa0 = *(const float4*)(align_w + 256 + 4 * lane);
    float4 wa1 = *(const float4*)(align_w + 384 + 4 * lane);

    float4 s0 = *(const float4*)(superatom + (size_t)m * DD + 4 * lane);
    float4 s1 = *(const float4*)(superatom + (size_t)m * DD + 128 + 4 * lane);
    float p = s0.x * ws0.x + s0.y * ws0.y + s0.z * ws0.z + s0.w * ws0.w
            + s1.x * ws1.x + s1.y * ws1.y + s1.z * ws1.z + s1.w * ws1.w;
#pragma unroll
    for (int off = 16; off > 0; off >>= 1) p += __shfl_xor_sync(0xffffffffu, p, off);
    float sdot = p + align_b[0];

    int beg = g_segstart[m], end = g_segstart[m + 1];
    float mmax = __int_as_float(0xff800000);
    float ssum = 0.f;
    float acc[8] = {0.f, 0.f, 0.f, 0.f, 0.f, 0.f, 0.f, 0.f};

    int i = beg;
    for (; i + 4 <= end; i += 4) {
        const float* ap = atom + (size_t)i * DD;
        float4 x0[4], x1[4];
#pragma unroll
        for (int q = 0; q < 4; q++) {
            x0[q] = *(const float4*)(ap + q * DD + 4 * lane);
            x1[q] = *(const float4*)(ap + q * DD + 128 + 4 * lane);
        }
        float d[4];
#pragma unroll
        for (int q = 0; q < 4; q++) {
            d[q] = x0[q].x * wa0.x + x0[q].y * wa0.y + x0[q].z * wa0.z + x0[q].w * wa0.w
                 + x1[q].x * wa1.x + x1[q].y * wa1.y + x1[q].z * wa1.z + x1[q].w * wa1.w;
        }
#pragma unroll
        for (int off = 16; off > 0; off >>= 1) {
            d[0] += __shfl_xor_sync(0xffffffffu, d[0], off);
            d[1] += __shfl_xor_sync(0xffffffffu, d[1], off);
            d[2] += __shfl_xor_sync(0xffffffffu, d[2], off);
            d[3] += __shfl_xor_sync(0xffffffffu, d[3], off);
        }
#pragma unroll
        for (int q = 0; q < 4; q++) {
            float sc = sdot + d[q];
            d[q] = sc >= 0.f ? sc : 0.01f * sc;
        }
        if (lane < 4) {
            float v = lane == 0 ? d[0] : (lane == 1 ? d[1] : (lane == 2 ? d[2] : d[3]));
            g_score[i + lane] = v;
        }
        float gm = fmaxf(fmaxf(d[0], d[1]), fmaxf(d[2], d[3]));
        float nm = fmaxf(mmax, gm);
        float scale = __expf(mmax - nm);
        float p0 = __expf(d[0] - nm);
        float p1 = __expf(d[1] - nm);
        float p2 = __expf(d[2] - nm);
        float p3 = __expf(d[3] - nm);
        ssum = ssum * scale + ((p0 + p1) + (p2 + p3));
        acc[0] = acc[0] * scale + p0 * x0[0].x + p1 * x0[1].x + p2 * x0[2].x + p3 * x0[3].x;
        acc[1] = acc[1] * scale + p0 * x0[0].y + p1 * x0[1].y + p2 * x0[2].y + p3 * x0[3].y;
        acc[2] = acc[2] * scale + p0 * x0[0].z + p1 * x0[1].z + p2 * x0[2].z + p3 * x0[3].z;
        acc[3] = acc[3] * scale + p0 * x0[0].w + p1 * x0[1].w + p2 * x0[2].w + p3 * x0[3].w;
        acc[4] = acc[4] * scale + p0 * x1[0].x + p1 * x1[1].x + p2 * x1[2].x + p3 * x1[3].x;
        acc[5] = acc[5] * scale + p0 * x1[0].y + p1 * x1[1].y + p2 * x1[2].y + p3 * x1[3].y;
        acc[6] = acc[6] * scale + p0 * x1[0].z + p1 * x1[1].z + p2 * x1[2].z + p3 * x1[3].z;
        acc[7] = acc[7] * scale + p0 * x1[0].w + p1 * x1[1].w + p2 * x1[2].w + p3 * x1[3].w;
        mmax = nm;
    }
    for (; i < end; i++) {
        const float* ap = atom + (size_t)i * DD;
        float4 a0 = *(const float4*)(ap + 4 * lane);
        float4 a1 = *(const float4*)(ap + 128 + 4 * lane);
        float d = a0.x * wa0.x + a0.y * wa0.y + a0.z * wa0.z + a0.w * wa0.w
                + a1.x * wa1.x + a1.y * wa1.y + a1.z * wa1.z + a1.w * wa1.w;
#pragma unroll
        for (int off = 16; off > 0; off >>= 1) d += __shfl_xor_sync(0xffffffffu, d, off);
        float sc = sdot + d;
        sc = sc >= 0.f ? sc : 0.01f * sc;
        if (lane == 0) g_score[i] = sc;

        float nm = fmaxf(mmax, sc);
        float scale = __expf(mmax - nm);
        float pz = __expf(sc - nm);
        ssum = ssum * scale + pz;
        acc[0] = acc[0] * scale + pz * a0.x;
        acc[1] = acc[1] * scale + pz * a0.y;
        acc[2] = acc[2] * scale + pz * a0.z;
        acc[3] = acc[3] * scale + pz * a0.w;
        acc[4] = acc[4] * scale + pz * a1.x;
        acc[5] = acc[5] * scale + pz * a1.y;
        acc[6] = acc[6] * scale + pz * a1.z;
        acc[7] = acc[7] * scale + pz * a1.w;
        mmax = nm;
    }

    float inv = 1.f / (ssum + EPS_SM);
    // store tf32-rounded: g_pooled is consumed only by the tf32 GEMM,
    // so this is bit-identical to the old in-loop cvt.
    float4 o0 = make_float4(rna_tf32f(acc[0] * inv), rna_tf32f(acc[1] * inv),
                            rna_tf32f(acc[2] * inv), rna_tf32f(acc[3] * inv));
    float4 o1 = make_float4(rna_tf32f(acc[4] * inv), rna_tf32f(acc[5] * inv),
                            rna_tf32f(acc[6] * inv), rna_tf32f(acc[7] * inv));
    *(float4*)(g_pooled + (size_t)m * DD + 4 * lane) = o0;
    *(float4*)(g_pooled + (size_t)m * DD + 128 + 4 * lane) = o1;
    if (lane == 0) {
        g_segmax[m] = mmax;
        g_segS[m] = ssum;
        g_sumw[m] = ssum * inv;
    }
}

__global__ void k_attw(const void* __restrict__ mi, int n, float* __restrict__ outw) {
    int i = blockIdx.x * blockDim.x + threadIdx.x;
    if (i >= n) return;
    int m = load_idx(mi, i, g_is32);
    outw[i] = __expf(g_score[i] - g_segmax[m]) / (g_segS[m] + EPS_SM);
}

// ---------------- tf32 mma.sync GEMM: C[i,j] = sum_k A[i,k]*B[j,k], K=256 --
// 128x128 tile, 512 threads = 16 warps (4m x 4n), warp tile 32x32.
// Inputs MUST be pre-rounded to tf32 (rna) — NO cvt in the mainloop
// (R13 profile: cvt was ~40% of hot-loop issue slots at issue=47.7%).
// 16 K-chunks of 16, 2-stage cp.async, 40KB dynamic smem, 2 CTAs/SM.
// mode 0: C = acc + colv[j]
// mode 1: C = tf32_round(elu(acc + rowv[i]*colv[j]))  (ctx only feeds GEMM)
#define SROW 20
#define STAGE_F 5120
#define B_OFF 2560

__global__ __launch_bounds__(512, 2)
void k_gemm_mma(const float* __restrict__ A, const float* __restrict__ B,
                float* __restrict__ C, int Ncols,
                const float* __restrict__ colv, const float* __restrict__ rowv, int mode) {
    extern __shared__ float dynsm[];
    const int t = threadIdx.x;
    const int lane = t & 31;
    const int wid = t >> 5;         // 0..15
    const int wm = wid >> 2;        // 0..3 (32-row slice)
    const int wn = wid & 3;         // 0..3 (32-col slice)
    const int rb = blockIdx.y * 128, cb = blockIdx.x * 128;

    const uint32_t sbase = smem_u32(dynsm);

    const int lrow = t >> 2;
    const int lq4 = (t & 3) * 4;
    const float* ga = A + (size_t)(rb + lrow) * DD + lq4;
    const float* gb = B + (size_t)(cb + lrow) * DD + lq4;
    const uint32_t sa_off = (uint32_t)(lrow * SROW + lq4) * 4u;

#define LOAD_CHUNK(c)                                                                    \
    {                                                                                    \
        uint32_t st_ = sbase + ((c) & 1) * (STAGE_F * 4u);                               \
        asm volatile("cp.async.cg.shared.global [%0], [%1], 16;"                         \
                     :: "r"(st_ + sa_off), "l"(ga + (c) * 16) : "memory");               \
        asm volatile("cp.async.cg.shared.global [%0], [%1], 16;"                         \
                     :: "r"(st_ + B_OFF * 4u + sa_off), "l"(gb + (c) * 16) : "memory");  \
        asm volatile("cp.async.commit_group;" ::: "memory");                             \
    }

    float acc[2][4][4];
#pragma unroll
    for (int i = 0; i < 2; i++)
#pragma unroll
        for (int j = 0; j < 4; j++)
#pragma unroll
            for (int q = 0; q < 4; q++) acc[i][j][q] = 0.f;

    LOAD_CHUNK(0);
    LOAD_CHUNK(1);

    const int lq = lane >> 2;   // 0..7
    const int lr = lane & 3;    // 0..3

    for (int c = 0; c < 16; c++) {
        if (c < 15) asm volatile("cp.async.wait_group 1;" ::: "memory");
        else        asm volatile("cp.async.wait_group 0;" ::: "memory");
        __syncthreads();

        const float* As = dynsm + (c & 1) * STAGE_F;
        const float* Bs = As + B_OFF;

#pragma unroll
        for (int k0 = 0; k0 < 16; k0 += 8) {
            uint32_t bfr[4][2];
#pragma unroll
            for (int j = 0; j < 4; j++) {
                int nrow = wn * 32 + j * 8 + lq;
                bfr[j][0] = __float_as_uint(Bs[nrow * SROW + k0 + lr]);
                bfr[j][1] = __float_as_uint(Bs[nrow * SROW + k0 + lr + 4]);
            }
#pragma unroll
            for (int i = 0; i < 2; i++) {
                int r0 = wm * 32 + i * 16;
                uint32_t a0 = __float_as_uint(As[(r0 + lq) * SROW + k0 + lr]);
                uint32_t a1 = __float_as_uint(As[(r0 + 8 + lq) * SROW + k0 + lr]);
                uint32_t a2 = __float_as_uint(As[(r0 + lq) * SROW + k0 + lr + 4]);
                uint32_t a3 = __float_as_uint(As[(r0 + 8 + lq) * SROW + k0 + lr + 4]);
#pragma unroll
                for (int j = 0; j < 4; j++) {
                    asm volatile(
                        "mma.sync.aligned.m16n8k8.row.col.f32.tf32.tf32.f32 "
                        "{%0,%1,%2,%3}, {%4,%5,%6,%7}, {%8,%9}, {%0,%1,%2,%3};"
                        : "+f"(acc[i][j][0]), "+f"(acc[i][j][1]),
                          "+f"(acc[i][j][2]), "+f"(acc[i][j][3])
                        : "r"(a0), "r"(a1), "r"(a2), "r"(a3),
                          "r"(bfr[j][0]), "r"(bfr[j][1]));
                }
            }
        }
        __syncthreads();
        if (c + 2 < 16) LOAD_CHUNK(c + 2);
    }

#pragma unroll
    for (int i = 0; i < 2; i++) {
        int r = rb + wm * 32 + i * 16 + lq;
        float rv0 = mode ? rowv[r] : 0.f;
        float rv1 = mode ? rowv[r + 8] : 0.f;
#pragma unroll
        for (int j = 0; j < 4; j++) {
            int col = cb + wn * 32 + j * 8 + 2 * lr;
            float cv0 = colv[col], cv1 = colv[col + 1];
            float x0 = acc[i][j][0], x1 = acc[i][j][1];
            float x2 = acc[i][j][2], x3 = acc[i][j][3];
            if (mode) {
                x0 += rv0 * cv0; x1 += rv0 * cv1;
                x2 += rv1 * cv0; x3 += rv1 * cv1;
                x0 = x0 > 0.f ? x0 : expm1f(x0);
                x1 = x1 > 0.f ? x1 : expm1f(x1);
                x2 = x2 > 0.f ? x2 : expm1f(x2);
                x3 = x3 > 0.f ? x3 : expm1f(x3);
                x0 = rna_tf32f(x0); x1 = rna_tf32f(x1);
                x2 = rna_tf32f(x2); x3 = rna_tf32f(x3);
            } else {
                x0 += cv0; x1 += cv1; x2 += cv0; x3 += cv1;
            }
            *(float2*)(C + (size_t)r * Ncols + col) = make_float2(x0, x1);
            *(float2*)(C + (size_t)(r + 8) * Ncols + col) = make_float2(x2, x3);
        }
    }
#undef LOAD_CHUNK
}

// ---------------- GRU gate combine ----------------
__global__ void k_gru(const float* __restrict__ superatom, float* __restrict__ out, int Mmol) {
    int i = blockIdx.x * blockDim.x + threadIdx.x;
    if (i >= Mmol * DD) return;
    int m = i >> 8, d = i & 255;
    size_t b = (size_t)m * 3 * DD + d;
    float xr = g_gx[b],          hr = g_gh[b];
    float xz = g_gx[b + DD],     hz = g_gh[b + DD];
    float xn = g_gx[b + 2 * DD], hn = g_gh[b + 2 * DD];
    float r = 1.f / (1.f + __expf(-(xr + hr)));
    float z = 1.f / (1.f + __expf(-(xz + hz)));
    float n = tanhf(xn + r * hn);
    float h = superatom[i];
    out[i] = (1.f - z) * n + z * h;
}

// ---------------- launch ----------------
// Fork-join across streams (R12/R13 proven).  Streams/events created ONCE and
// reused on every call so nothing is allocated during capture and the
// post-teardown memory baseline is preserved.
static cudaStream_t s_s1 = nullptr, s_s2 = nullptr;
static cudaEvent_t  s_evFork = nullptr, s_evPool = nullptr, s_evJ1 = nullptr, s_evJ2 = nullptr;

extern "C" void kernel_launch(void* const* d_in, const int* in_sizes, int n_in,
                              void* d_out, int out_size) {
    const float* superatom = (const float*)d_in[0];
    const float* atom      = (const float*)d_in[1];
    const void*  molidx    = d_in[2];
    const float* align_w   = (const float*)d_in[3];
    const float* align_b   = (const float*)d_in[4];
    const float* attend_w  = (const float*)d_in[5];
    const float* attend_b  = (const float*)d_in[6];
    const float* bn_gamma  = (const float*)d_in[7];
    const float* bn_beta   = (const float*)d_in[8];
    const float* bn_mean   = (const float*)d_in[9];
    const float* bn_var    = (const float*)d_in[10];
    const float* gru_wih   = (const float*)d_in[11];
    const float* gru_whh   = (const float*)d_in[12];
    const float* gru_bih   = (const float*)d_in[13];
    const float* gru_bhh   = (const float*)d_in[14];

    int Mmol = in_sizes[0] / DD;
    int n    = in_sizes[2];
    float* out = (float*)d_out;

    void* vp;
    float *p_pooled, *p_ctx, *p_gx, *p_gh, *p_Wa, *p_cvec, *p_sumw;
    float *p_sa, *p_whh, *p_wih;
    cudaGetSymbolAddress(&vp, g_pooled); p_pooled = (float*)vp;
    cudaGetSymbolAddress(&vp, g_ctx);    p_ctx    = (float*)vp;
    cudaGetSymbolAddress(&vp, g_gx);     p_gx     = (float*)vp;
    cudaGetSymbolAddress(&vp, g_gh);     p_gh     = (float*)vp;
    cudaGetSymbolAddress(&vp, g_Wa);     p_Wa     = (float*)vp;
    cudaGetSymbolAddress(&vp, g_cvec);   p_cvec   = (float*)vp;
    cudaGetSymbolAddress(&vp, g_sumw);   p_sumw   = (float*)vp;
    cudaGetSymbolAddress(&vp, g_sa);     p_sa     = (float*)vp;
    cudaGetSymbolAddress(&vp, g_whh_r);  p_whh    = (float*)vp;
    cudaGetSymbolAddress(&vp, g_wih_r);  p_wih    = (float*)vp;

    if (!s_s1) {
        cudaStreamCreateWithFlags(&s_s1, cudaStreamNonBlocking);
        cudaStreamCreateWithFlags(&s_s2, cudaStreamNonBlocking);
        cudaEventCreateWithFlags(&s_evFork, cudaEventDisableTiming);
        cudaEventCreateWithFlags(&s_evPool, cudaEventDisableTiming);
        cudaEventCreateWithFlags(&s_evJ1,   cudaEventDisableTiming);
        cudaEventCreateWithFlags(&s_evJ2,   cudaEventDisableTiming);
    }

    const int DYNSM = 2 * STAGE_F * 4;  // 40960 bytes (< 48KB default)

    int nb = (n + 255) / 256;
    dim3 g1(DD / 128, Mmol / 128);
    dim3 g2(3 * DD / 128, Mmol / 128);

    // ---- main (capture) stream ----
    k_zero_flag<<<1, 1>>>();
    k_round<<<(Mmol * DD / 4 + 255) / 256, 256>>>(superatom, p_sa, Mmol * DD / 4);
    k_round<<<(3 * DD * DD / 4 + 255) / 256, 256>>>(gru_whh, p_whh, 3 * DD * DD / 4);

    // fork: independent whh-GEMM on s1 (pre-rounded inputs ready via evFork)
    cudaEventRecord(s_evFork, 0);
    cudaStreamWaitEvent(s_s1, s_evFork, 0);
    k_gemm_mma<<<g2, 512, DYNSM, s_s1>>>(p_sa, p_whh, p_gh, 3 * DD, gru_bhh, nullptr, 0);
    cudaEventRecord(s_evJ1, s_s1);

    k_round<<<(3 * DD * DD / 4 + 255) / 256, 256>>>(gru_wih, p_wih, 3 * DD * DD / 4);
    k_detect<<<nb, 256>>>(molidx, n);
    k_segstart<<<nb, 256>>>(molidx, n, Mmol);
    k_weff<<<DD, 256>>>(attend_w, attend_b, bn_gamma, bn_beta, bn_mean, bn_var);
    k_pool<<<(Mmol + 7) / 8, 256>>>(superatom, atom, molidx, align_w, align_b, Mmol);

    // fork: attention-weight output on s2 (depends only on pool)
    cudaEventRecord(s_evPool, 0);
    cudaStreamWaitEvent(s_s2, s_evPool, 0);
    k_attw<<<nb, 256, 0, s_s2>>>(molidx, n, out + (size_t)Mmol * DD);
    cudaEventRecord(s_evJ2, s_s2);

    // dependent GEMM chain on main stream
    k_gemm_mma<<<g1, 512, DYNSM>>>(p_pooled, p_Wa, p_ctx, DD, p_cvec, p_sumw, 1);
    k_gemm_mma<<<g2, 512, DYNSM>>>(p_ctx, p_wih, p_gx, 3 * DD, gru_bih, nullptr, 0);

    // join both branches, then the final combine
    cudaStreamWaitEvent(0, s_evJ1, 0);
    cudaStreamWaitEvent(0, s_evJ2, 0);
    k_gru<<<(Mmol * DD + 255) / 256, 256>>>(superatom, out, Mmol);
}

// round 15
// speedup vs baseline: 1.0272x; 1.0272x over previous
#include <cuda_runtime.h>
#include <math.h>
#include <stdint.h>

#define NATOMS_MAX 500000
#define MMOL_MAX   16384
#define DD         256
#define EPS_BN 1e-6f
#define EPS_SM 1e-8f

// ---------------- scratch (static device globals; no allocs) ----------------
__device__ float g_score[NATOMS_MAX];
__device__ float g_pooled[MMOL_MAX * DD];
__device__ float g_ctx[MMOL_MAX * DD];
__device__ float g_gx[MMOL_MAX * 3 * DD];
__device__ float g_gh[MMOL_MAX * 3 * DD];
__device__ float g_segmax[MMOL_MAX];
__device__ float g_segS[MMOL_MAX];
__device__ float g_sumw[MMOL_MAX];
__device__ int   g_segstart[MMOL_MAX + 1];
__device__ float g_Wa[DD * DD];
__device__ float g_cvec[DD];
__device__ int   g_is32;

__device__ __forceinline__ int load_idx(const void* mi, int i, int is32) {
    if (is32) return ((const int*)mi)[i];
    return (int)((const long long*)mi)[i];
}

__device__ __forceinline__ uint32_t smem_u32(const void* p) {
    uint32_t a;
    asm("{ .reg .u64 t; cvta.to.shared.u64 t, %1; cvt.u32.u64 %0, t; }" : "=r"(a) : "l"(p));
    return a;
}
__device__ __forceinline__ uint32_t to_tf32(float f) {
    uint32_t u;
    asm("cvt.rna.tf32.f32 %0, %1;" : "=r"(u) : "f"(f));
    return u;
}
__device__ __forceinline__ float rna_tf32f(float f) {
    uint32_t u;
    asm("cvt.rna.tf32.f32 %0, %1;" : "=r"(u) : "f"(f));
    return __uint_as_float(u);
}

// ---------------- tiny setup kernels ----------------
__global__ void k_zero_flag() { g_is32 = 0; }

__global__ void k_detect(const void* __restrict__ mi, int n) {
    int i = blockIdx.x * blockDim.x + threadIdx.x;
    if (i >= n) return;
    if ((i & 1) && ((const int*)mi)[i] != 0) atomicOr(&g_is32, 1);
}

__global__ void k_segstart(const void* __restrict__ mi, int n, int Mmol) {
    int i = blockIdx.x * blockDim.x + threadIdx.x;
    if (i >= n) return;
    int is32 = g_is32;
    int cur = load_idx(mi, i, is32);
    if (i == 0) {
        for (int m = 0; m <= cur; m++) g_segstart[m] = 0;
    } else {
        int prev = load_idx(mi, i - 1, is32);
        for (int m = prev + 1; m <= cur; m++) g_segstart[m] = i;
    }
    if (i == n - 1) {
        for (int m = cur + 1; m <= Mmol; m++) g_segstart[m] = n;
    }
}

__global__ void k_weff(const float* __restrict__ attend_w, const float* __restrict__ attend_b,
                       const float* __restrict__ gamma, const float* __restrict__ beta,
                       const float* __restrict__ mean, const float* __restrict__ var) {
    int i = blockIdx.x * blockDim.x + threadIdx.x;
    if (i >= DD * DD) return;
    int j = i >> 8;
    float g = gamma[j] * rsqrtf(var[j] + EPS_BN);
    g_Wa[i] = rna_tf32f(attend_w[i] * g);   // idempotent under GEMM's in-loop cvt
    if ((i & 255) == 0)
        g_cvec[j] = g * (attend_b[j] - mean[j]) + beta[j];
}

// ---------------- fused align-score + online softmax + weighted pooling ----
__global__ void k_pool(const float* __restrict__ superatom, const float* __restrict__ atom,
                       const void* __restrict__ mi, const float* __restrict__ align_w,
                       const float* __restrict__ align_b, int Mmol) {
    int warp = (blockIdx.x * blockDim.x + threadIdx.x) >> 5;
    int lane = threadIdx.x & 31;
    if (warp >= Mmol) return;
    int m = warp;

    float4 ws0 = *(const float4*)(align_w + 4 * lane);
    float4 ws1 = *(const float4*)(align_w + 128 + 4 * lane);
    float4 wa0 = *(const float4*)(align_w + 256 + 4 * lane);
    float4 wa1 = *(const float4*)(align_w + 384 + 4 * lane);

    float4 s0 = *(const float4*)(superatom + (size_t)m * DD + 4 * lane);
    float4 s1 = *(const float4*)(superatom + (size_t)m * DD + 128 + 4 * lane);
    float p = s0.x * ws0.x + s0.y * ws0.y + s0.z * ws0.z + s0.w * ws0.w
            + s1.x * ws1.x + s1.y * ws1.y + s1.z * ws1.z + s1.w * ws1.w;
#pragma unroll
    for (int off = 16; off > 0; off >>= 1) p += __shfl_xor_sync(0xffffffffu, p, off);
    float sdot = p + align_b[0];

    int beg = g_segstart[m], end = g_segstart[m + 1];
    float mmax = __int_as_float(0xff800000);
    float ssum = 0.f;
    float acc[8] = {0.f, 0.f, 0.f, 0.f, 0.f, 0.f, 0.f, 0.f};

    int i = beg;
    for (; i + 4 <= end; i += 4) {
        const float* ap = atom + (size_t)i * DD;
        float4 x0[4], x1[4];
#pragma unroll
        for (int q = 0; q < 4; q++) {
            x0[q] = *(const float4*)(ap + q * DD + 4 * lane);
            x1[q] = *(const float4*)(ap + q * DD + 128 + 4 * lane);
        }
        float d[4];
#pragma unroll
        for (int q = 0; q < 4; q++) {
            d[q] = x0[q].x * wa0.x + x0[q].y * wa0.y + x0[q].z * wa0.z + x0[q].w * wa0.w
                 + x1[q].x * wa1.x + x1[q].y * wa1.y + x1[q].z * wa1.z + x1[q].w * wa1.w;
        }
#pragma unroll
        for (int off = 16; off > 0; off >>= 1) {
            d[0] += __shfl_xor_sync(0xffffffffu, d[0], off);
            d[1] += __shfl_xor_sync(0xffffffffu, d[1], off);
            d[2] += __shfl_xor_sync(0xffffffffu, d[2], off);
            d[3] += __shfl_xor_sync(0xffffffffu, d[3], off);
        }
#pragma unroll
        for (int q = 0; q < 4; q++) {
            float sc = sdot + d[q];
            d[q] = sc >= 0.f ? sc : 0.01f * sc;
        }
        if (lane < 4) {
            float v = lane == 0 ? d[0] : (lane == 1 ? d[1] : (lane == 2 ? d[2] : d[3]));
            g_score[i + lane] = v;
        }
        float gm = fmaxf(fmaxf(d[0], d[1]), fmaxf(d[2], d[3]));
        float nm = fmaxf(mmax, gm);
        float scale = __expf(mmax - nm);
        float p0 = __expf(d[0] - nm);
        float p1 = __expf(d[1] - nm);
        float p2 = __expf(d[2] - nm);
        float p3 = __expf(d[3] - nm);
        ssum = ssum * scale + ((p0 + p1) + (p2 + p3));
        acc[0] = acc[0] * scale + p0 * x0[0].x + p1 * x0[1].x + p2 * x0[2].x + p3 * x0[3].x;
        acc[1] = acc[1] * scale + p0 * x0[0].y + p1 * x0[1].y + p2 * x0[2].y + p3 * x0[3].y;
        acc[2] = acc[2] * scale + p0 * x0[0].z + p1 * x0[1].z + p2 * x0[2].z + p3 * x0[3].z;
        acc[3] = acc[3] * scale + p0 * x0[0].w + p1 * x0[1].w + p2 * x0[2].w + p3 * x0[3].w;
        acc[4] = acc[4] * scale + p0 * x1[0].x + p1 * x1[1].x + p2 * x1[2].x + p3 * x1[3].x;
        acc[5] = acc[5] * scale + p0 * x1[0].y + p1 * x1[1].y + p2 * x1[2].y + p3 * x1[3].y;
        acc[6] = acc[6] * scale + p0 * x1[0].z + p1 * x1[1].z + p2 * x1[2].z + p3 * x1[3].z;
        acc[7] = acc[7] * scale + p0 * x1[0].w + p1 * x1[1].w + p2 * x1[2].w + p3 * x1[3].w;
        mmax = nm;
    }
    for (; i < end; i++) {
        const float* ap = atom + (size_t)i * DD;
        float4 a0 = *(const float4*)(ap + 4 * lane);
        float4 a1 = *(const float4*)(ap + 128 + 4 * lane);
        float d = a0.x * wa0.x + a0.y * wa0.y + a0.z * wa0.z + a0.w * wa0.w
                + a1.x * wa1.x + a1.y * wa1.y + a1.z * wa1.z + a1.w * wa1.w;
#pragma unroll
        for (int off = 16; off > 0; off >>= 1) d += __shfl_xor_sync(0xffffffffu, d, off);
        float sc = sdot + d;
        sc = sc >= 0.f ? sc : 0.01f * sc;
        if (lane == 0) g_score[i] = sc;

        float nm = fmaxf(mmax, sc);
        float scale = __expf(mmax - nm);
        float pz = __expf(sc - nm);
        ssum = ssum * scale + pz;
        acc[0] = acc[0] * scale + pz * a0.x;
        acc[1] = acc[1] * scale + pz * a0.y;
        acc[2] = acc[2] * scale + pz * a0.z;
        acc[3] = acc[3] * scale + pz * a0.w;
        acc[4] = acc[4] * scale + pz * a1.x;
        acc[5] = acc[5] * scale + pz * a1.y;
        acc[6] = acc[6] * scale + pz * a1.z;
        acc[7] = acc[7] * scale + pz * a1.w;
        mmax = nm;
    }

    float inv = 1.f / (ssum + EPS_SM);
    float4 o0 = make_float4(acc[0] * inv, acc[1] * inv, acc[2] * inv, acc[3] * inv);
    float4 o1 = make_float4(acc[4] * inv, acc[5] * inv, acc[6] * inv, acc[7] * inv);
    *(float4*)(g_pooled + (size_t)m * DD + 4 * lane) = o0;
    *(float4*)(g_pooled + (size_t)m * DD + 128 + 4 * lane) = o1;
    if (lane == 0) {
        g_segmax[m] = mmax;
        g_segS[m] = ssum;
        g_sumw[m] = ssum * inv;
    }
}

__global__ void k_attw(const void* __restrict__ mi, int n, float* __restrict__ outw) {
    int i = blockIdx.x * blockDim.x + threadIdx.x;
    if (i >= n) return;
    int m = load_idx(mi, i, g_is32);
    outw[i] = __expf(g_score[i] - g_segmax[m]) / (g_segS[m] + EPS_SM);
}

// ---------------- tf32 mma.sync GEMM: C[i,j] = sum_k A[i,k]*B[j,k], K=256 --
// 128x128 tile, 512 threads = 16 warps (4m x 4n), warp tile 32x32 (R13 base).
// CHANGE vs R13: 4-stage cp.async pipeline (80KB smem) -> 3 iterations of
// load->use slack (~1500cyc), fully covering L2 latency that a 2-stage pipe
// exposed every chunk (R13/R14 showed duration invariant to instruction mix
// => latency-bubble bound).  Trailing per-chunk __syncthreads removed: the
// load at iter c targets stage (c-1)&3, already protected by iter-c's
// leading barrier.
// mode 0: C = acc + colv[j]
// mode 1: C = elu(acc + rowv[i]*colv[j])
#define SROW 20
#define STAGE_F 5120
#define B_OFF 2560
#define NSTAGE 4
#define DYNSM_B (NSTAGE * STAGE_F * 4)   // 81920 bytes

__global__ __launch_bounds__(512, 2)
void k_gemm_mma(const float* __restrict__ A, const float* __restrict__ B,
                float* __restrict__ C, int Ncols,
                const float* __restrict__ colv, const float* __restrict__ rowv, int mode) {
    extern __shared__ float dynsm[];
    const int t = threadIdx.x;
    const int lane = t & 31;
    const int wid = t >> 5;         // 0..15
    const int wm = wid >> 2;        // 0..3 (32-row slice)
    const int wn = wid & 3;         // 0..3 (32-col slice)
    const int rb = blockIdx.y * 128, cb = blockIdx.x * 128;

    const uint32_t sbase = smem_u32(dynsm);

    const int lrow = t >> 2;
    const int lq4 = (t & 3) * 4;
    const float* ga = A + (size_t)(rb + lrow) * DD + lq4;
    const float* gb = B + (size_t)(cb + lrow) * DD + lq4;
    const uint32_t sa_off = (uint32_t)(lrow * SROW + lq4) * 4u;

#define LOAD_CHUNK(c)                                                                    \
    {                                                                                    \
        uint32_t st_ = sbase + ((c) & 3) * (STAGE_F * 4u);                               \
        asm volatile("cp.async.cg.shared.global [%0], [%1], 16;"                         \
                     :: "r"(st_ + sa_off), "l"(ga + (c) * 16) : "memory");               \
        asm volatile("cp.async.cg.shared.global [%0], [%1], 16;"                         \
                     :: "r"(st_ + B_OFF * 4u + sa_off), "l"(gb + (c) * 16) : "memory");  \
        asm volatile("cp.async.commit_group;" ::: "memory");                             \
    }

    float acc[2][4][4];
#pragma unroll
    for (int i = 0; i < 2; i++)
#pragma unroll
        for (int j = 0; j < 4; j++)
#pragma unroll
            for (int q = 0; q < 4; q++) acc[i][j][q] = 0.f;

    LOAD_CHUNK(0);
    LOAD_CHUNK(1);
    LOAD_CHUNK(2);

    const int lq = lane >> 2;   // 0..7
    const int lr = lane & 3;    // 0..3

    for (int c = 0; c < 16; c++) {
        if (c <= 13)      asm volatile("cp.async.wait_group 2;" ::: "memory");
        else if (c == 14) asm volatile("cp.async.wait_group 1;" ::: "memory");
        else              asm volatile("cp.async.wait_group 0;" ::: "memory");
        __syncthreads();

        const float* As = dynsm + (c & 3) * STAGE_F;
        const float* Bs = As + B_OFF;

#pragma unroll
        for (int k0 = 0; k0 < 16; k0 += 8) {
            uint32_t bfr[4][2];
#pragma unroll
            for (int j = 0; j < 4; j++) {
                int nrow = wn * 32 + j * 8 + lq;
                bfr[j][0] = to_tf32(Bs[nrow * SROW + k0 + lr]);
                bfr[j][1] = to_tf32(Bs[nrow * SROW + k0 + lr + 4]);
            }
#pragma unroll
            for (int i = 0; i < 2; i++) {
                int r0 = wm * 32 + i * 16;
                uint32_t a0 = to_tf32(As[(r0 + lq) * SROW + k0 + lr]);
                uint32_t a1 = to_tf32(As[(r0 + 8 + lq) * SROW + k0 + lr]);
                uint32_t a2 = to_tf32(As[(r0 + lq) * SROW + k0 + lr + 4]);
                uint32_t a3 = to_tf32(As[(r0 + 8 + lq) * SROW + k0 + lr + 4]);
#pragma unroll
                for (int j = 0; j < 4; j++) {
                    asm volatile(
                        "mma.sync.aligned.m16n8k8.row.col.f32.tf32.tf32.f32 "
                        "{%0,%1,%2,%3}, {%4,%5,%6,%7}, {%8,%9}, {%0,%1,%2,%3};"
                        : "+f"(acc[i][j][0]), "+f"(acc[i][j][1]),
                          "+f"(acc[i][j][2]), "+f"(acc[i][j][3])
                        : "r"(a0), "r"(a1), "r"(a2), "r"(a3),
                          "r"(bfr[j][0]), "r"(bfr[j][1]));
                }
            }
        }
        if (c + 3 < 16) LOAD_CHUNK(c + 3);
    }

#pragma unroll
    for (int i = 0; i < 2; i++) {
        int r = rb + wm * 32 + i * 16 + lq;
        float rv0 = mode ? rowv[r] : 0.f;
        float rv1 = mode ? rowv[r + 8] : 0.f;
#pragma unroll
        for (int j = 0; j < 4; j++) {
            int col = cb + wn * 32 + j * 8 + 2 * lr;
            float cv0 = colv[col], cv1 = colv[col + 1];
            float x0 = acc[i][j][0], x1 = acc[i][j][1];
            float x2 = acc[i][j][2], x3 = acc[i][j][3];
            if (mode) {
                x0 += rv0 * cv0; x1 += rv0 * cv1;
                x2 += rv1 * cv0; x3 += rv1 * cv1;
                x0 = x0 > 0.f ? x0 : expm1f(x0);
                x1 = x1 > 0.f ? x1 : expm1f(x1);
                x2 = x2 > 0.f ? x2 : expm1f(x2);
                x3 = x3 > 0.f ? x3 : expm1f(x3);
            } else {
                x0 += cv0; x1 += cv1; x2 += cv0; x3 += cv1;
            }
            *(float2*)(C + (size_t)r * Ncols + col) = make_float2(x0, x1);
            *(float2*)(C + (size_t)(r + 8) * Ncols + col) = make_float2(x2, x3);
        }
    }
#undef LOAD_CHUNK
}

// ---------------- GRU gate combine ----------------
__global__ void k_gru(const float* __restrict__ superatom, float* __restrict__ out, int Mmol) {
    int i = blockIdx.x * blockDim.x + threadIdx.x;
    if (i >= Mmol * DD) return;
    int m = i >> 8, d = i & 255;
    size_t b = (size_t)m * 3 * DD + d;
    float xr = g_gx[b],          hr = g_gh[b];
    float xz = g_gx[b + DD],     hz = g_gh[b + DD];
    float xn = g_gx[b + 2 * DD], hn = g_gh[b + 2 * DD];
    float r = 1.f / (1.f + __expf(-(xr + hr)));
    float z = 1.f / (1.f + __expf(-(xz + hz)));
    float n = tanhf(xn + r * hn);
    float h = superatom[i];
    out[i] = (1.f - z) * n + z * h;
}

// ---------------- launch ----------------
// Fork-join across streams (R12/R13 proven).  Streams/events created ONCE and
// reused on every call so nothing is allocated during capture and the
// post-teardown memory baseline is preserved.
static cudaStream_t s_s1 = nullptr, s_s2 = nullptr;
static cudaEvent_t  s_evFork = nullptr, s_evPool = nullptr, s_evJ1 = nullptr, s_evJ2 = nullptr;

extern "C" void kernel_launch(void* const* d_in, const int* in_sizes, int n_in,
                              void* d_out, int out_size) {
    const float* superatom = (const float*)d_in[0];
    const float* atom      = (const float*)d_in[1];
    const void*  molidx    = d_in[2];
    const float* align_w   = (const float*)d_in[3];
    const float* align_b   = (const float*)d_in[4];
    const float* attend_w  = (const float*)d_in[5];
    const float* attend_b  = (const float*)d_in[6];
    const float* bn_gamma  = (const float*)d_in[7];
    const float* bn_beta   = (const float*)d_in[8];
    const float* bn_mean   = (const float*)d_in[9];
    const float* bn_var    = (const float*)d_in[10];
    const float* gru_wih   = (const float*)d_in[11];
    const float* gru_whh   = (const float*)d_in[12];
    const float* gru_bih   = (const float*)d_in[13];
    const float* gru_bhh   = (const float*)d_in[14];

    int Mmol = in_sizes[0] / DD;
    int n    = in_sizes[2];
    float* out = (float*)d_out;

    void* vp;
    float *p_pooled, *p_ctx, *p_gx, *p_gh, *p_Wa, *p_cvec, *p_sumw;
    cudaGetSymbolAddress(&vp, g_pooled); p_pooled = (float*)vp;
    cudaGetSymbolAddress(&vp, g_ctx);    p_ctx    = (float*)vp;
    cudaGetSymbolAddress(&vp, g_gx);     p_gx     = (float*)vp;
    cudaGetSymbolAddress(&vp, g_gh);     p_gh     = (float*)vp;
    cudaGetSymbolAddress(&vp, g_Wa);     p_Wa     = (float*)vp;
    cudaGetSymbolAddress(&vp, g_cvec);   p_cvec   = (float*)vp;
    cudaGetSymbolAddress(&vp, g_sumw);   p_sumw   = (float*)vp;

    if (!s_s1) {
        cudaStreamCreateWithFlags(&s_s1, cudaStreamNonBlocking);
        cudaStreamCreateWithFlags(&s_s2, cudaStreamNonBlocking);
        cudaEventCreateWithFlags(&s_evFork, cudaEventDisableTiming);
        cudaEventCreateWithFlags(&s_evPool, cudaEventDisableTiming);
        cudaEventCreateWithFlags(&s_evJ1,   cudaEventDisableTiming);
        cudaEventCreateWithFlags(&s_evJ2,   cudaEventDisableTiming);
    }
    cudaFuncSetAttribute(k_gemm_mma, cudaFuncAttributeMaxDynamicSharedMemorySize, DYNSM_B);

    int nb = (n + 255) / 256;
    dim3 g1(DD / 128, Mmol / 128);
    dim3 g2(3 * DD / 128, Mmol / 128);

    // ---- main (capture) stream: attention path ----
    k_zero_flag<<<1, 1>>>();
    k_detect<<<nb, 256>>>(molidx, n);
    k_segstart<<<nb, 256>>>(molidx, n, Mmol);

    // fork: independent whh-GEMM on s1 (overlaps k_weff + k_pool)
    cudaEventRecord(s_evFork, 0);
    cudaStreamWaitEvent(s_s1, s_evFork, 0);
    k_gemm_mma<<<g2, 512, DYNSM_B, s_s1>>>(superatom, gru_whh, p_gh, 3 * DD, gru_bhh, nullptr, 0);
    cudaEventRecord(s_evJ1, s_s1);

    k_weff<<<DD, 256>>>(attend_w, attend_b, bn_gamma, bn_beta, bn_mean, bn_var);
    k_pool<<<(Mmol + 7) / 8, 256>>>(superatom, atom, molidx, align_w, align_b, Mmol);

    // fork: attention-weight output on s2 (depends only on pool)
    cudaEventRecord(s_evPool, 0);
    cudaStreamWaitEvent(s_s2, s_evPool, 0);
    k_attw<<<nb, 256, 0, s_s2>>>(molidx, n, out + (size_t)Mmol * DD);
    cudaEventRecord(s_evJ2, s_s2);

    // dependent GEMM chain on main stream
    k_gemm_mma<<<g1, 512, DYNSM_B>>>(p_pooled, p_Wa, p_ctx, DD, p_cvec, p_sumw, 1);
    k_gemm_mma<<<g2, 512, DYNSM_B>>>(p_ctx, gru_wih, p_gx, 3 * DD, gru_bih, nullptr, 0);

    // join both branches, then the final combine
    cudaStreamWaitEvent(0, s_evJ1, 0);
    cudaStreamWaitEvent(0, s_evJ2, 0);
    k_gru<<<(Mmol * DD + 255) / 256, 256>>>(superatom, out, Mmol);
}

// round 16
// speedup vs baseline: 1.0358x; 1.0084x over previous
#include <cuda_runtime.h>
#include <math.h>
#include <stdint.h>

#define NATOMS_MAX 500000
#define MMOL_MAX   16384
#define DD         256
#define EPS_BN 1e-6f
#define EPS_SM 1e-8f

// ---------------- scratch (static device globals; no allocs) ----------------
__device__ float g_score[NATOMS_MAX];
__device__ float g_pooled[MMOL_MAX * DD];
__device__ float g_ctx[MMOL_MAX * DD];
__device__ float g_gx[MMOL_MAX * 3 * DD];
__device__ float g_gh[MMOL_MAX * 3 * DD];
__device__ float g_segmax[MMOL_MAX];
__device__ float g_segS[MMOL_MAX];
__device__ float g_sumw[MMOL_MAX];
__device__ int   g_segstart[MMOL_MAX + 1];
__device__ float g_Wa[DD * DD];
__device__ float g_cvec[DD];
__device__ int   g_is32;

__device__ __forceinline__ int load_idx(const void* mi, int i, int is32) {
    if (is32) return ((const int*)mi)[i];
    return (int)((const long long*)mi)[i];
}

__device__ __forceinline__ uint32_t smem_u32(const void* p) {
    uint32_t a;
    asm("{ .reg .u64 t; cvta.to.shared.u64 t, %1; cvt.u32.u64 %0, t; }" : "=r"(a) : "l"(p));
    return a;
}
__device__ __forceinline__ uint32_t to_tf32(float f) {
    uint32_t u;
    asm("cvt.rna.tf32.f32 %0, %1;" : "=r"(u) : "f"(f));
    return u;
}
__device__ __forceinline__ float rna_tf32f(float f) {
    uint32_t u;
    asm("cvt.rna.tf32.f32 %0, %1;" : "=r"(u) : "f"(f));
    return __uint_as_float(u);
}

// ---------------- tiny setup kernels ----------------
__global__ void k_zero_flag() { g_is32 = 0; }

__global__ void k_detect(const void* __restrict__ mi, int n) {
    int i = blockIdx.x * blockDim.x + threadIdx.x;
    if (i >= n) return;
    if ((i & 1) && ((const int*)mi)[i] != 0) atomicOr(&g_is32, 1);
}

__global__ void k_segstart(const void* __restrict__ mi, int n, int Mmol) {
    int i = blockIdx.x * blockDim.x + threadIdx.x;
    if (i >= n) return;
    int is32 = g_is32;
    int cur = load_idx(mi, i, is32);
    if (i == 0) {
        for (int m = 0; m <= cur; m++) g_segstart[m] = 0;
    } else {
        int prev = load_idx(mi, i - 1, is32);
        for (int m = prev + 1; m <= cur; m++) g_segstart[m] = i;
    }
    if (i == n - 1) {
        for (int m = cur + 1; m <= Mmol; m++) g_segstart[m] = n;
    }
}

__global__ void k_weff(const float* __restrict__ attend_w, const float* __restrict__ attend_b,
                       const float* __restrict__ gamma, const float* __restrict__ beta,
                       const float* __restrict__ mean, const float* __restrict__ var) {
    int i = blockIdx.x * blockDim.x + threadIdx.x;
    if (i >= DD * DD) return;
    int j = i >> 8;
    float g = gamma[j] * rsqrtf(var[j] + EPS_BN);
    g_Wa[i] = rna_tf32f(attend_w[i] * g);   // idempotent under GEMM's in-loop cvt
    if ((i & 255) == 0)
        g_cvec[j] = g * (attend_b[j] - mean[j]) + beta[j];
}

// ---------------- fused align-score + online softmax + weighted pooling ----
__global__ void k_pool(const float* __restrict__ superatom, const float* __restrict__ atom,
                       const void* __restrict__ mi, const float* __restrict__ align_w,
                       const float* __restrict__ align_b, int Mmol) {
    int warp = (blockIdx.x * blockDim.x + threadIdx.x) >> 5;
    int lane = threadIdx.x & 31;
    if (warp >= Mmol) return;
    int m = warp;

    float4 ws0 = *(const float4*)(align_w + 4 * lane);
    float4 ws1 = *(const float4*)(align_w + 128 + 4 * lane);
    float4 wa0 = *(const float4*)(align_w + 256 + 4 * lane);
    float4 wa1 = *(const float4*)(align_w + 384 + 4 * lane);

    float4 s0 = *(const float4*)(superatom + (size_t)m * DD + 4 * lane);
    float4 s1 = *(const float4*)(superatom + (size_t)m * DD + 128 + 4 * lane);
    float p = s0.x * ws0.x + s0.y * ws0.y + s0.z * ws0.z + s0.w * ws0.w
            + s1.x * ws1.x + s1.y * ws1.y + s1.z * ws1.z + s1.w * ws1.w;
#pragma unroll
    for (int off = 16; off > 0; off >>= 1) p += __shfl_xor_sync(0xffffffffu, p, off);
    float sdot = p + align_b[0];

    int beg = g_segstart[m], end = g_segstart[m + 1];
    float mmax = __int_as_float(0xff800000);
    float ssum = 0.f;
    float acc[8] = {0.f, 0.f, 0.f, 0.f, 0.f, 0.f, 0.f, 0.f};

    int i = beg;
    for (; i + 4 <= end; i += 4) {
        const float* ap = atom + (size_t)i * DD;
        float4 x0[4], x1[4];
#pragma unroll
        for (int q = 0; q < 4; q++) {
            x0[q] = *(const float4*)(ap + q * DD + 4 * lane);
            x1[q] = *(const float4*)(ap + q * DD + 128 + 4 * lane);
        }
        float d[4];
#pragma unroll
        for (int q = 0; q < 4; q++) {
            d[q] = x0[q].x * wa0.x + x0[q].y * wa0.y + x0[q].z * wa0.z + x0[q].w * wa0.w
                 + x1[q].x * wa1.x + x1[q].y * wa1.y + x1[q].z * wa1.z + x1[q].w * wa1.w;
        }
#pragma unroll
        for (int off = 16; off > 0; off >>= 1) {
            d[0] += __shfl_xor_sync(0xffffffffu, d[0], off);
            d[1] += __shfl_xor_sync(0xffffffffu, d[1], off);
            d[2] += __shfl_xor_sync(0xffffffffu, d[2], off);
            d[3] += __shfl_xor_sync(0xffffffffu, d[3], off);
        }
#pragma unroll
        for (int q = 0; q < 4; q++) {
            float sc = sdot + d[q];
            d[q] = sc >= 0.f ? sc : 0.01f * sc;
        }
        if (lane < 4) {
            float v = lane == 0 ? d[0] : (lane == 1 ? d[1] : (lane == 2 ? d[2] : d[3]));
            g_score[i + lane] = v;
        }
        float gm = fmaxf(fmaxf(d[0], d[1]), fmaxf(d[2], d[3]));
        float nm = fmaxf(mmax, gm);
        float scale = __expf(mmax - nm);
        float p0 = __expf(d[0] - nm);
        float p1 = __expf(d[1] - nm);
        float p2 = __expf(d[2] - nm);
        float p3 = __expf(d[3] - nm);
        ssum = ssum * scale + ((p0 + p1) + (p2 + p3));
        acc[0] = acc[0] * scale + p0 * x0[0].x + p1 * x0[1].x + p2 * x0[2].x + p3 * x0[3].x;
        acc[1] = acc[1] * scale + p0 * x0[0].y + p1 * x0[1].y + p2 * x0[2].y + p3 * x0[3].y;
        acc[2] = acc[2] * scale + p0 * x0[0].z + p1 * x0[1].z + p2 * x0[2].z + p3 * x0[3].z;
        acc[3] = acc[3] * scale + p0 * x0[0].w + p1 * x0[1].w + p2 * x0[2].w + p3 * x0[3].w;
        acc[4] = acc[4] * scale + p0 * x1[0].x + p1 * x1[1].x + p2 * x1[2].x + p3 * x1[3].x;
        acc[5] = acc[5] * scale + p0 * x1[0].y + p1 * x1[1].y + p2 * x1[2].y + p3 * x1[3].y;
        acc[6] = acc[6] * scale + p0 * x1[0].z + p1 * x1[1].z + p2 * x1[2].z + p3 * x1[3].z;
        acc[7] = acc[7] * scale + p0 * x1[0].w + p1 * x1[1].w + p2 * x1[2].w + p3 * x1[3].w;
        mmax = nm;
    }
    for (; i < end; i++) {
        const float* ap = atom + (size_t)i * DD;
        float4 a0 = *(const float4*)(ap + 4 * lane);
        float4 a1 = *(const float4*)(ap + 128 + 4 * lane);
        float d = a0.x * wa0.x + a0.y * wa0.y + a0.z * wa0.z + a0.w * wa0.w
                + a1.x * wa1.x + a1.y * wa1.y + a1.z * wa1.z + a1.w * wa1.w;
#pragma unroll
        for (int off = 16; off > 0; off >>= 1) d += __shfl_xor_sync(0xffffffffu, d, off);
        float sc = sdot + d;
        sc = sc >= 0.f ? sc : 0.01f * sc;
        if (lane == 0) g_score[i] = sc;

        float nm = fmaxf(mmax, sc);
        float scale = __expf(mmax - nm);
        float pz = __expf(sc - nm);
        ssum = ssum * scale + pz;
        acc[0] = acc[0] * scale + pz * a0.x;
        acc[1] = acc[1] * scale + pz * a0.y;
        acc[2] = acc[2] * scale + pz * a0.z;
        acc[3] = acc[3] * scale + pz * a0.w;
        acc[4] = acc[4] * scale + pz * a1.x;
        acc[5] = acc[5] * scale + pz * a1.y;
        acc[6] = acc[6] * scale + pz * a1.z;
        acc[7] = acc[7] * scale + pz * a1.w;
        mmax = nm;
    }

    float inv = 1.f / (ssum + EPS_SM);
    float4 o0 = make_float4(acc[0] * inv, acc[1] * inv, acc[2] * inv, acc[3] * inv);
    float4 o1 = make_float4(acc[4] * inv, acc[5] * inv, acc[6] * inv, acc[7] * inv);
    *(float4*)(g_pooled + (size_t)m * DD + 4 * lane) = o0;
    *(float4*)(g_pooled + (size_t)m * DD + 128 + 4 * lane) = o1;
    if (lane == 0) {
        g_segmax[m] = mmax;
        g_segS[m] = ssum;
        g_sumw[m] = ssum * inv;
    }
}

__global__ void k_attw(const void* __restrict__ mi, int n, float* __restrict__ outw) {
    int i = blockIdx.x * blockDim.x + threadIdx.x;
    if (i >= n) return;
    int m = load_idx(mi, i, g_is32);
    outw[i] = __expf(g_score[i] - g_segmax[m]) / (g_segS[m] + EPS_SM);
}

// ---------------- tf32 mma.sync GEMM (R13 config — proven floor) -----------
// 128x128 tile, 512 threads = 16 warps (4m x 4n), warp tile 32x32.
// 16 K-chunks of 16, 2-stage cp.async, 40KB dynamic smem, 2 CTAs/SM.
// mode 0: C = acc + colv[j]
// mode 1: C = elu(acc + rowv[i]*colv[j])
#define SROW 20
#define STAGE_F 5120
#define B_OFF 2560

__global__ __launch_bounds__(512, 2)
void k_gemm_mma(const float* __restrict__ A, const float* __restrict__ B,
                float* __restrict__ C, int Ncols,
                const float* __restrict__ colv, const float* __restrict__ rowv, int mode) {
    extern __shared__ float dynsm[];
    const int t = threadIdx.x;
    const int lane = t & 31;
    const int wid = t >> 5;         // 0..15
    const int wm = wid >> 2;        // 0..3 (32-row slice)
    const int wn = wid & 3;         // 0..3 (32-col slice)
    const int rb = blockIdx.y * 128, cb = blockIdx.x * 128;

    const uint32_t sbase = smem_u32(dynsm);

    const int lrow = t >> 2;
    const int lq4 = (t & 3) * 4;
    const float* ga = A + (size_t)(rb + lrow) * DD + lq4;
    const float* gb = B + (size_t)(cb + lrow) * DD + lq4;
    const uint32_t sa_off = (uint32_t)(lrow * SROW + lq4) * 4u;

#define LOAD_CHUNK(c)                                                                    \
    {                                                                                    \
        uint32_t st_ = sbase + ((c) & 1) * (STAGE_F * 4u);                               \
        asm volatile("cp.async.cg.shared.global [%0], [%1], 16;"                         \
                     :: "r"(st_ + sa_off), "l"(ga + (c) * 16) : "memory");               \
        asm volatile("cp.async.cg.shared.global [%0], [%1], 16;"                         \
                     :: "r"(st_ + B_OFF * 4u + sa_off), "l"(gb + (c) * 16) : "memory");  \
        asm volatile("cp.async.commit_group;" ::: "memory");                             \
    }

    float acc[2][4][4];
#pragma unroll
    for (int i = 0; i < 2; i++)
#pragma unroll
        for (int j = 0; j < 4; j++)
#pragma unroll
            for (int q = 0; q < 4; q++) acc[i][j][q] = 0.f;

    LOAD_CHUNK(0);
    LOAD_CHUNK(1);

    const int lq = lane >> 2;   // 0..7
    const int lr = lane & 3;    // 0..3

    for (int c = 0; c < 16; c++) {
        if (c < 15) asm volatile("cp.async.wait_group 1;" ::: "memory");
        else        asm volatile("cp.async.wait_group 0;" ::: "memory");
        __syncthreads();

        const float* As = dynsm + (c & 1) * STAGE_F;
        const float* Bs = As + B_OFF;

#pragma unroll
        for (int k0 = 0; k0 < 16; k0 += 8) {
            uint32_t bfr[4][2];
#pragma unroll
            for (int j = 0; j < 4; j++) {
                int nrow = wn * 32 + j * 8 + lq;
                bfr[j][0] = to_tf32(Bs[nrow * SROW + k0 + lr]);
                bfr[j][1] = to_tf32(Bs[nrow * SROW + k0 + lr + 4]);
            }
#pragma unroll
            for (int i = 0; i < 2; i++) {
                int r0 = wm * 32 + i * 16;
                uint32_t a0 = to_tf32(As[(r0 + lq) * SROW + k0 + lr]);
                uint32_t a1 = to_tf32(As[(r0 + 8 + lq) * SROW + k0 + lr]);
                uint32_t a2 = to_tf32(As[(r0 + lq) * SROW + k0 + lr + 4]);
                uint32_t a3 = to_tf32(As[(r0 + 8 + lq) * SROW + k0 + lr + 4]);
#pragma unroll
                for (int j = 0; j < 4; j++) {
                    asm volatile(
                        "mma.sync.aligned.m16n8k8.row.col.f32.tf32.tf32.f32 "
                        "{%0,%1,%2,%3}, {%4,%5,%6,%7}, {%8,%9}, {%0,%1,%2,%3};"
                        : "+f"(acc[i][j][0]), "+f"(acc[i][j][1]),
                          "+f"(acc[i][j][2]), "+f"(acc[i][j][3])
                        : "r"(a0), "r"(a1), "r"(a2), "r"(a3),
                          "r"(bfr[j][0]), "r"(bfr[j][1]));
                }
            }
        }
        __syncthreads();
        if (c + 2 < 16) LOAD_CHUNK(c + 2);
    }

#pragma unroll
    for (int i = 0; i < 2; i++) {
        int r = rb + wm * 32 + i * 16 + lq;
        float rv0 = mode ? rowv[r] : 0.f;
        float rv1 = mode ? rowv[r + 8] : 0.f;
#pragma unroll
        for (int j = 0; j < 4; j++) {
            int col = cb + wn * 32 + j * 8 + 2 * lr;
            float cv0 = colv[col], cv1 = colv[col + 1];
            float x0 = acc[i][j][0], x1 = acc[i][j][1];
            float x2 = acc[i][j][2], x3 = acc[i][j][3];
            if (mode) {
                x0 += rv0 * cv0; x1 += rv0 * cv1;
                x2 += rv1 * cv0; x3 += rv1 * cv1;
                x0 = x0 > 0.f ? x0 : expm1f(x0);
                x1 = x1 > 0.f ? x1 : expm1f(x1);
                x2 = x2 > 0.f ? x2 : expm1f(x2);
                x3 = x3 > 0.f ? x3 : expm1f(x3);
            } else {
                x0 += cv0; x1 += cv1; x2 += cv0; x3 += cv1;
            }
            *(float2*)(C + (size_t)r * Ncols + col) = make_float2(x0, x1);
            *(float2*)(C + (size_t)(r + 8) * Ncols + col) = make_float2(x2, x3);
        }
    }
#undef LOAD_CHUNK
}

// ---------------- GRU gate combine ----------------
__global__ void k_gru(const float* __restrict__ superatom, float* __restrict__ out, int Mmol) {
    int i = blockIdx.x * blockDim.x + threadIdx.x;
    if (i >= Mmol * DD) return;
    int m = i >> 8, d = i & 255;
    size_t b = (size_t)m * 3 * DD + d;
    float xr = g_gx[b],          hr = g_gh[b];
    float xz = g_gx[b + DD],     hz = g_gh[b + DD];
    float xn = g_gx[b + 2 * DD], hn = g_gh[b + 2 * DD];
    float r = 1.f / (1.f + __expf(-(xr + hr)));
    float z = 1.f / (1.f + __expf(-(xz + hz)));
    float n = tanhf(xn + r * hn);
    float h = superatom[i];
    out[i] = (1.f - z) * n + z * h;
}

// ---------------- launch ----------------
// Fork-join with stream PRIORITIES: the whh-GEMM runs on a LOWEST-priority
// stream so the DRAM-bound k_pool keeps its load warps scheduled first and
// the GEMM soaks spare issue slots (R15 analysis: ~90us of the runtime is
// pool<->GEMM contention).  k_weff moves off the critical path onto s2.
// Streams/events created ONCE and reused every call (incl. capture) so no
// device memory is allocated during capture.
static cudaStream_t s_s1 = nullptr, s_s2 = nullptr;
static cudaEvent_t  s_evFork = nullptr, s_evW = nullptr, s_evPool = nullptr,
                    s_evJ1 = nullptr, s_evJ2 = nullptr;

extern "C" void kernel_launch(void* const* d_in, const int* in_sizes, int n_in,
                              void* d_out, int out_size) {
    const float* superatom = (const float*)d_in[0];
    const float* atom      = (const float*)d_in[1];
    const void*  molidx    = d_in[2];
    const float* align_w   = (const float*)d_in[3];
    const float* align_b   = (const float*)d_in[4];
    const float* attend_w  = (const float*)d_in[5];
    const float* attend_b  = (const float*)d_in[6];
    const float* bn_gamma  = (const float*)d_in[7];
    const float* bn_beta   = (const float*)d_in[8];
    const float* bn_mean   = (const float*)d_in[9];
    const float* bn_var    = (const float*)d_in[10];
    const float* gru_wih   = (const float*)d_in[11];
    const float* gru_whh   = (const float*)d_in[12];
    const float* gru_bih   = (const float*)d_in[13];
    const float* gru_bhh   = (const float*)d_in[14];

    int Mmol = in_sizes[0] / DD;
    int n    = in_sizes[2];
    float* out = (float*)d_out;

    void* vp;
    float *p_pooled, *p_ctx, *p_gx, *p_gh, *p_Wa, *p_cvec, *p_sumw;
    cudaGetSymbolAddress(&vp, g_pooled); p_pooled = (float*)vp;
    cudaGetSymbolAddress(&vp, g_ctx);    p_ctx    = (float*)vp;
    cudaGetSymbolAddress(&vp, g_gx);     p_gx     = (float*)vp;
    cudaGetSymbolAddress(&vp, g_gh);     p_gh     = (float*)vp;
    cudaGetSymbolAddress(&vp, g_Wa);     p_Wa     = (float*)vp;
    cudaGetSymbolAddress(&vp, g_cvec);   p_cvec   = (float*)vp;
    cudaGetSymbolAddress(&vp, g_sumw);   p_sumw   = (float*)vp;

    if (!s_s1) {
        int prLow = 0, prHigh = 0;
        cudaDeviceGetStreamPriorityRange(&prLow, &prHigh);
        // prLow = numerically largest = LEAST priority
        cudaStreamCreateWithPriority(&s_s1, cudaStreamNonBlocking, prLow);
        cudaStreamCreateWithFlags(&s_s2, cudaStreamNonBlocking);
        cudaEventCreateWithFlags(&s_evFork, cudaEventDisableTiming);
        cudaEventCreateWithFlags(&s_evW,    cudaEventDisableTiming);
        cudaEventCreateWithFlags(&s_evPool, cudaEventDisableTiming);
        cudaEventCreateWithFlags(&s_evJ1,   cudaEventDisableTiming);
        cudaEventCreateWithFlags(&s_evJ2,   cudaEventDisableTiming);
    }

    const int DYNSM = 2 * STAGE_F * 4;  // 40960 bytes (< 48KB default)

    int nb = (n + 255) / 256;
    dim3 g1(DD / 128, Mmol / 128);
    dim3 g2(3 * DD / 128, Mmol / 128);

    // ---- main (capture) stream: attention critical path ----
    k_zero_flag<<<1, 1>>>();
    cudaEventRecord(s_evFork, 0);

    // fork 1: whh-GEMM at LOWEST priority on s1 (overlaps pool, yields slots)
    cudaStreamWaitEvent(s_s1, s_evFork, 0);
    k_gemm_mma<<<g2, 512, DYNSM, s_s1>>>(superatom, gru_whh, p_gh, 3 * DD, gru_bhh, nullptr, 0);
    cudaEventRecord(s_evJ1, s_s1);

    // fork 2: k_weff on s2 (pool does not read g_Wa; only ctx-GEMM does)
    cudaStreamWaitEvent(s_s2, s_evFork, 0);
    k_weff<<<DD, 256, 0, s_s2>>>(attend_w, attend_b, bn_gamma, bn_beta, bn_mean, bn_var);
    cudaEventRecord(s_evW, s_s2);

    k_detect<<<nb, 256>>>(molidx, n);
    k_segstart<<<nb, 256>>>(molidx, n, Mmol);
    k_pool<<<(Mmol + 7) / 8, 256>>>(superatom, atom, molidx, align_w, align_b, Mmol);

    // fork 3: attention-weight output on s2 (depends only on pool + detect)
    cudaEventRecord(s_evPool, 0);
    cudaStreamWaitEvent(s_s2, s_evPool, 0);
    k_attw<<<nb, 256, 0, s_s2>>>(molidx, n, out + (size_t)Mmol * DD);
    cudaEventRecord(s_evJ2, s_s2);

    // dependent GEMM chain on main stream (ctx-GEMM needs g_Wa from s2)
    cudaStreamWaitEvent(0, s_evW, 0);
    k_gemm_mma<<<g1, 512, DYNSM>>>(p_pooled, p_Wa, p_ctx, DD, p_cvec, p_sumw, 1);
    k_gemm_mma<<<g2, 512, DYNSM>>>(p_ctx, gru_wih, p_gx, 3 * DD, gru_bih, nullptr, 0);

    // join both branches, then the final combine
    cudaStreamWaitEvent(0, s_evJ1, 0);
    cudaStreamWaitEvent(0, s_evJ2, 0);
    k_gru<<<(Mmol * DD + 255) / 256, 256>>>(superatom, out, Mmol);
}

// round 17
// speedup vs baseline: 1.3056x; 1.2605x over previous
#include <cuda_runtime.h>
#include <cuda_fp16.h>
#include <math.h>
#include <stdint.h>

#define NATOMS_MAX 500000
#define MMOL_MAX   16384
#define DD         256
#define EPS_BN 1e-6f
#define EPS_SM 1e-8f

// ---------------- scratch (static device globals; no allocs) ----------------
__device__ float  g_score[NATOMS_MAX];
__device__ __half g_pooled_h[MMOL_MAX * DD];
__device__ __half g_ctx_h[MMOL_MAX * DD];
__device__ float  g_gx[MMOL_MAX * 3 * DD];
__device__ float  g_gh[MMOL_MAX * 3 * DD];
__device__ __half g_sa_h[MMOL_MAX * DD];
__device__ __half g_whh_h[3 * DD * DD];
__device__ __half g_wih_h[3 * DD * DD];
__device__ float  g_segmax[MMOL_MAX];
__device__ float  g_segS[MMOL_MAX];
__device__ float  g_sumw[MMOL_MAX];
__device__ int    g_segstart[MMOL_MAX + 1];
__device__ __half g_Wa_h[DD * DD];
__device__ float  g_cvec[DD];
__device__ int    g_is32;

__device__ __forceinline__ int load_idx(const void* mi, int i, int is32) {
    if (is32) return ((const int*)mi)[i];
    return (int)((const long long*)mi)[i];
}

__device__ __forceinline__ uint32_t smem_u32(const void* p) {
    uint32_t a;
    asm("{ .reg .u64 t; cvta.to.shared.u64 t, %1; cvt.u32.u64 %0, t; }" : "=r"(a) : "l"(p));
    return a;
}

// ---------------- tiny setup kernels ----------------
__global__ void k_zero_flag() { g_is32 = 0; }

__global__ void k_detect(const void* __restrict__ mi, int n) {
    int i = blockIdx.x * blockDim.x + threadIdx.x;
    if (i >= n) return;
    if ((i & 1) && ((const int*)mi)[i] != 0) atomicOr(&g_is32, 1);
}

__global__ void k_segstart(const void* __restrict__ mi, int n, int Mmol) {
    int i = blockIdx.x * blockDim.x + threadIdx.x;
    if (i >= n) return;
    int is32 = g_is32;
    int cur = load_idx(mi, i, is32);
    if (i == 0) {
        for (int m = 0; m <= cur; m++) g_segstart[m] = 0;
    } else {
        int prev = load_idx(mi, i - 1, is32);
        for (int m = prev + 1; m <= cur; m++) g_segstart[m] = i;
    }
    if (i == n - 1) {
        for (int m = cur + 1; m <= Mmol; m++) g_segstart[m] = n;
    }
}

// f32 -> fp16 copy, 8 elements per thread
__global__ void k_tohalf(const float* __restrict__ in, __half* __restrict__ out, int n8) {
    int i = blockIdx.x * blockDim.x + threadIdx.x;
    if (i >= n8) return;
    float4 v0 = ((const float4*)in)[2 * i];
    float4 v1 = ((const float4*)in)[2 * i + 1];
    __half2 h[4];
    h[0] = __floats2half2_rn(v0.x, v0.y);
    h[1] = __floats2half2_rn(v0.z, v0.w);
    h[2] = __floats2half2_rn(v1.x, v1.y);
    h[3] = __floats2half2_rn(v1.z, v1.w);
    ((uint4*)out)[i] = *(uint4*)h;
}

__global__ void k_weff(const float* __restrict__ attend_w, const float* __restrict__ attend_b,
                       const float* __restrict__ gamma, const float* __restrict__ beta,
                       const float* __restrict__ mean, const float* __restrict__ var) {
    int i = blockIdx.x * blockDim.x + threadIdx.x;
    if (i >= DD * DD) return;
    int j = i >> 8;
    float g = gamma[j] * rsqrtf(var[j] + EPS_BN);
    g_Wa_h[i] = __float2half(attend_w[i] * g);
    if ((i & 255) == 0)
        g_cvec[j] = g * (attend_b[j] - mean[j]) + beta[j];
}

// ---------------- fused align-score + online softmax + weighted pooling ----
__global__ void k_pool(const float* __restrict__ superatom, const float* __restrict__ atom,
                       const void* __restrict__ mi, const float* __restrict__ align_w,
                       const float* __restrict__ align_b, int Mmol) {
    int warp = (blockIdx.x * blockDim.x + threadIdx.x) >> 5;
    int lane = threadIdx.x & 31;
    if (warp >= Mmol) return;
    int m = warp;

    float4 ws0 = *(const float4*)(align_w + 4 * lane);
    float4 ws1 = *(const float4*)(align_w + 128 + 4 * lane);
    float4 wa0 = *(const float4*)(align_w + 256 + 4 * lane);
    float4 wa1 = *(const float4*)(align_w + 384 + 4 * lane);

    float4 s0 = *(const float4*)(superatom + (size_t)m * DD + 4 * lane);
    float4 s1 = *(const float4*)(superatom + (size_t)m * DD + 128 + 4 * lane);
    float p = s0.x * ws0.x + s0.y * ws0.y + s0.z * ws0.z + s0.w * ws0.w
            + s1.x * ws1.x + s1.y * ws1.y + s1.z * ws1.z + s1.w * ws1.w;
#pragma unroll
    for (int off = 16; off > 0; off >>= 1) p += __shfl_xor_sync(0xffffffffu, p, off);
    float sdot = p + align_b[0];

    int beg = g_segstart[m], end = g_segstart[m + 1];
    float mmax = __int_as_float(0xff800000);
    float ssum = 0.f;
    float acc[8] = {0.f, 0.f, 0.f, 0.f, 0.f, 0.f, 0.f, 0.f};

    int i = beg;
    for (; i + 4 <= end; i += 4) {
        const float* ap = atom + (size_t)i * DD;
        float4 x0[4], x1[4];
#pragma unroll
        for (int q = 0; q < 4; q++) {
            x0[q] = *(const float4*)(ap + q * DD + 4 * lane);
            x1[q] = *(const float4*)(ap + q * DD + 128 + 4 * lane);
        }
        float d[4];
#pragma unroll
        for (int q = 0; q < 4; q++) {
            d[q] = x0[q].x * wa0.x + x0[q].y * wa0.y + x0[q].z * wa0.z + x0[q].w * wa0.w
                 + x1[q].x * wa1.x + x1[q].y * wa1.y + x1[q].z * wa1.z + x1[q].w * wa1.w;
        }
#pragma unroll
        for (int off = 16; off > 0; off >>= 1) {
            d[0] += __shfl_xor_sync(0xffffffffu, d[0], off);
            d[1] += __shfl_xor_sync(0xffffffffu, d[1], off);
            d[2] += __shfl_xor_sync(0xffffffffu, d[2], off);
            d[3] += __shfl_xor_sync(0xffffffffu, d[3], off);
        }
#pragma unroll
        for (int q = 0; q < 4; q++) {
            float sc = sdot + d[q];
            d[q] = sc >= 0.f ? sc : 0.01f * sc;
        }
        if (lane < 4) {
            float v = lane == 0 ? d[0] : (lane == 1 ? d[1] : (lane == 2 ? d[2] : d[3]));
            g_score[i + lane] = v;
        }
        float gm = fmaxf(fmaxf(d[0], d[1]), fmaxf(d[2], d[3]));
        float nm = fmaxf(mmax, gm);
        float scale = __expf(mmax - nm);
        float p0 = __expf(d[0] - nm);
        float p1 = __expf(d[1] - nm);
        float p2 = __expf(d[2] - nm);
        float p3 = __expf(d[3] - nm);
        ssum = ssum * scale + ((p0 + p1) + (p2 + p3));
        acc[0] = acc[0] * scale + p0 * x0[0].x + p1 * x0[1].x + p2 * x0[2].x + p3 * x0[3].x;
        acc[1] = acc[1] * scale + p0 * x0[0].y + p1 * x0[1].y + p2 * x0[2].y + p3 * x0[3].y;
        acc[2] = acc[2] * scale + p0 * x0[0].z + p1 * x0[1].z + p2 * x0[2].z + p3 * x0[3].z;
        acc[3] = acc[3] * scale + p0 * x0[0].w + p1 * x0[1].w + p2 * x0[2].w + p3 * x0[3].w;
        acc[4] = acc[4] * scale + p0 * x1[0].x + p1 * x1[1].x + p2 * x1[2].x + p3 * x1[3].x;
        acc[5] = acc[5] * scale + p0 * x1[0].y + p1 * x1[1].y + p2 * x1[2].y + p3 * x1[3].y;
        acc[6] = acc[6] * scale + p0 * x1[0].z + p1 * x1[1].z + p2 * x1[2].z + p3 * x1[3].z;
        acc[7] = acc[7] * scale + p0 * x1[0].w + p1 * x1[1].w + p2 * x1[2].w + p3 * x1[3].w;
        mmax = nm;
    }
    for (; i < end; i++) {
        const float* ap = atom + (size_t)i * DD;
        float4 a0 = *(const float4*)(ap + 4 * lane);
        float4 a1 = *(const float4*)(ap + 128 + 4 * lane);
        float d = a0.x * wa0.x + a0.y * wa0.y + a0.z * wa0.z + a0.w * wa0.w
                + a1.x * wa1.x + a1.y * wa1.y + a1.z * wa1.z + a1.w * wa1.w;
#pragma unroll
        for (int off = 16; off > 0; off >>= 1) d += __shfl_xor_sync(0xffffffffu, d, off);
        float sc = sdot + d;
        sc = sc >= 0.f ? sc : 0.01f * sc;
        if (lane == 0) g_score[i] = sc;

        float nm = fmaxf(mmax, sc);
        float scale = __expf(mmax - nm);
        float pz = __expf(sc - nm);
        ssum = ssum * scale + pz;
        acc[0] = acc[0] * scale + pz * a0.x;
        acc[1] = acc[1] * scale + pz * a0.y;
        acc[2] = acc[2] * scale + pz * a0.z;
        acc[3] = acc[3] * scale + pz * a0.w;
        acc[4] = acc[4] * scale + pz * a1.x;
        acc[5] = acc[5] * scale + pz * a1.y;
        acc[6] = acc[6] * scale + pz * a1.z;
        acc[7] = acc[7] * scale + pz * a1.w;
        mmax = nm;
    }

    float inv = 1.f / (ssum + EPS_SM);
    // pooled is consumed only by the fp16 GEMM -> store fp16 directly
    __half* ph = g_pooled_h + (size_t)m * DD;
    *(__half2*)(ph + 4 * lane)       = __floats2half2_rn(acc[0] * inv, acc[1] * inv);
    *(__half2*)(ph + 4 * lane + 2)   = __floats2half2_rn(acc[2] * inv, acc[3] * inv);
    *(__half2*)(ph + 128 + 4 * lane)     = __floats2half2_rn(acc[4] * inv, acc[5] * inv);
    *(__half2*)(ph + 128 + 4 * lane + 2) = __floats2half2_rn(acc[6] * inv, acc[7] * inv);
    if (lane == 0) {
        g_segmax[m] = mmax;
        g_segS[m] = ssum;
        g_sumw[m] = ssum * inv;
    }
}

__global__ void k_attw(const void* __restrict__ mi, int n, float* __restrict__ outw) {
    int i = blockIdx.x * blockDim.x + threadIdx.x;
    if (i >= n) return;
    int m = load_idx(mi, i, g_is32);
    outw[i] = __expf(g_score[i] - g_segmax[m]) / (g_segS[m] + EPS_SM);
}

// ---------------- fp16 mma.sync GEMM: C[i,j] = sum_k A[i,k]*B[j,k], K=256 --
// 128x128 tile, 512 threads = 16 warps (4m x 4n), warp tile 32x32.
// m16n8k16.f16 with f32 accumulate: fp16 mantissa == tf32 mantissa (10 bits),
// so precision matches the tf32 path, but each MMA does 2x the MACs and smem
// traffic halves.  8 K-chunks of 32, 2-stage cp.async, 40KB smem, 2 CTAs/SM.
// mode 0: C(float) = acc + colv[j]
// mode 1: Ch(half) = elu(acc + rowv[i]*colv[j])   (ctx only feeds next GEMM)
#define SROW_H 40                    // 32 data + 8 pad halves (80B rows)
#define MAT_H (128 * SROW_H)         // 5120 halves per matrix per stage
#define STAGE_H (2 * MAT_H)          // 10240 halves per stage (20KB)

__global__ __launch_bounds__(512, 2)
void k_gemm_h(const __half* __restrict__ A, const __half* __restrict__ B,
              float* __restrict__ C, __half* __restrict__ Ch, int Ncols,
              const float* __restrict__ colv, const float* __restrict__ rowv, int mode) {
    extern __shared__ __half dynsm_h[];
    const int t = threadIdx.x;
    const int lane = t & 31;
    const int wid = t >> 5;         // 0..15
    const int wm = wid >> 2;        // 0..3 (32-row slice)
    const int wn = wid & 3;         // 0..3 (32-col slice)
    const int rb = blockIdx.y * 128, cb = blockIdx.x * 128;

    const uint32_t sbase = smem_u32(dynsm_h);

    // staging: thread t -> row t>>2, eighth (t&3)*8 halves; 1x16B per matrix
    const int lrow = t >> 2;
    const int lh8 = (t & 3) * 8;
    const __half* ga = A + (size_t)(rb + lrow) * DD + lh8;
    const __half* gb = B + (size_t)(cb + lrow) * DD + lh8;
    const uint32_t sa_off = (uint32_t)(lrow * SROW_H + lh8) * 2u;

#define LOAD_CHUNK(c)                                                                    \
    {                                                                                    \
        uint32_t st_ = sbase + ((c) & 1) * (STAGE_H * 2u);                               \
        asm volatile("cp.async.cg.shared.global [%0], [%1], 16;"                         \
                     :: "r"(st_ + sa_off), "l"(ga + (c) * 32) : "memory");               \
        asm volatile("cp.async.cg.shared.global [%0], [%1], 16;"                         \
                     :: "r"(st_ + MAT_H * 2u + sa_off), "l"(gb + (c) * 32) : "memory");  \
        asm volatile("cp.async.commit_group;" ::: "memory");                             \
    }

    float acc[2][4][4];
#pragma unroll
    for (int i = 0; i < 2; i++)
#pragma unroll
        for (int j = 0; j < 4; j++)
#pragma unroll
            for (int q = 0; q < 4; q++) acc[i][j][q] = 0.f;

    LOAD_CHUNK(0);
    LOAD_CHUNK(1);

    const int lq = lane >> 2;   // 0..7
    const int lr = lane & 3;    // 0..3

    for (int c = 0; c < 8; c++) {
        if (c < 7) asm volatile("cp.async.wait_group 1;" ::: "memory");
        else       asm volatile("cp.async.wait_group 0;" ::: "memory");
        __syncthreads();

        const __half* As = dynsm_h + (c & 1) * STAGE_H;
        const __half* Bs = As + MAT_H;

#pragma unroll
        for (int kk = 0; kk < 32; kk += 16) {
            // B fragments: b0 = B[n=lq'][k=kk+2lr..+1], b1 = k+8 (contiguous half2)
            uint32_t bfr[4][2];
#pragma unroll
            for (int j = 0; j < 4; j++) {
                int nrow = wn * 32 + j * 8 + lq;
                bfr[j][0] = *(const uint32_t*)(Bs + nrow * SROW_H + kk + 2 * lr);
                bfr[j][1] = *(const uint32_t*)(Bs + nrow * SROW_H + kk + 2 * lr + 8);
            }
#pragma unroll
            for (int i = 0; i < 2; i++) {
                int r0 = wm * 32 + i * 16;
                uint32_t a0 = *(const uint32_t*)(As + (r0 + lq) * SROW_H + kk + 2 * lr);
                uint32_t a1 = *(const uint32_t*)(As + (r0 + 8 + lq) * SROW_H + kk + 2 * lr);
                uint32_t a2 = *(const uint32_t*)(As + (r0 + lq) * SROW_H + kk + 2 * lr + 8);
                uint32_t a3 = *(const uint32_t*)(As + (r0 + 8 + lq) * SROW_H + kk + 2 * lr + 8);
#pragma unroll
                for (int j = 0; j < 4; j++) {
                    asm volatile(
                        "mma.sync.aligned.m16n8k16.row.col.f32.f16.f16.f32 "
                        "{%0,%1,%2,%3}, {%4,%5,%6,%7}, {%8,%9}, {%0,%1,%2,%3};"
                        : "+f"(acc[i][j][0]), "+f"(acc[i][j][1]),
                          "+f"(acc[i][j][2]), "+f"(acc[i][j][3])
                        : "r"(a0), "r"(a1), "r"(a2), "r"(a3),
                          "r"(bfr[j][0]), "r"(bfr[j][1]));
                }
            }
        }
        __syncthreads();
        if (c + 2 < 8) LOAD_CHUNK(c + 2);
    }

#pragma unroll
    for (int i = 0; i < 2; i++) {
        int r = rb + wm * 32 + i * 16 + lq;
        float rv0 = mode ? rowv[r] : 0.f;
        float rv1 = mode ? rowv[r + 8] : 0.f;
#pragma unroll
        for (int j = 0; j < 4; j++) {
            int col = cb + wn * 32 + j * 8 + 2 * lr;
            float cv0 = colv[col], cv1 = colv[col + 1];
            float x0 = acc[i][j][0], x1 = acc[i][j][1];
            float x2 = acc[i][j][2], x3 = acc[i][j][3];
            if (mode) {
                x0 += rv0 * cv0; x1 += rv0 * cv1;
                x2 += rv1 * cv0; x3 += rv1 * cv1;
                x0 = x0 > 0.f ? x0 : expm1f(x0);
                x1 = x1 > 0.f ? x1 : expm1f(x1);
                x2 = x2 > 0.f ? x2 : expm1f(x2);
                x3 = x3 > 0.f ? x3 : expm1f(x3);
                *(__half2*)(Ch + (size_t)r * Ncols + col) = __floats2half2_rn(x0, x1);
                *(__half2*)(Ch + (size_t)(r + 8) * Ncols + col) = __floats2half2_rn(x2, x3);
            } else {
                x0 += cv0; x1 += cv1; x2 += cv0; x3 += cv1;
                *(float2*)(C + (size_t)r * Ncols + col) = make_float2(x0, x1);
                *(float2*)(C + (size_t)(r + 8) * Ncols + col) = make_float2(x2, x3);
            }
        }
    }
#undef LOAD_CHUNK
}

// ---------------- GRU gate combine ----------------
__global__ void k_gru(const float* __restrict__ superatom, float* __restrict__ out, int Mmol) {
    int i = blockIdx.x * blockDim.x + threadIdx.x;
    if (i >= Mmol * DD) return;
    int m = i >> 8, d = i & 255;
    size_t b = (size_t)m * 3 * DD + d;
    float xr = g_gx[b],          hr = g_gh[b];
    float xz = g_gx[b + DD],     hz = g_gh[b + DD];
    float xn = g_gx[b + 2 * DD], hn = g_gh[b + 2 * DD];
    float r = 1.f / (1.f + __expf(-(xr + hr)));
    float z = 1.f / (1.f + __expf(-(xz + hz)));
    float n = tanhf(xn + r * hn);
    float h = superatom[i];
    out[i] = (1.f - z) * n + z * h;
}

// ---------------- launch ----------------
// Fork-join (R12/R13 proven) + fp16 GEMM path.  Streams/events created ONCE
// and reused on every call so nothing is allocated during capture and the
// post-teardown memory baseline is preserved.  whh-GEMM runs on a lowest-
// priority stream under the DRAM-bound k_pool.
static cudaStream_t s_s1 = nullptr, s_s2 = nullptr;
static cudaEvent_t  s_evFork = nullptr, s_evW = nullptr, s_evPool = nullptr,
                    s_evJ1 = nullptr, s_evJ2 = nullptr;

extern "C" void kernel_launch(void* const* d_in, const int* in_sizes, int n_in,
                              void* d_out, int out_size) {
    const float* superatom = (const float*)d_in[0];
    const float* atom      = (const float*)d_in[1];
    const void*  molidx    = d_in[2];
    const float* align_w   = (const float*)d_in[3];
    const float* align_b   = (const float*)d_in[4];
    const float* attend_w  = (const float*)d_in[5];
    const float* attend_b  = (const float*)d_in[6];
    const float* bn_gamma  = (const float*)d_in[7];
    const float* bn_beta   = (const float*)d_in[8];
    const float* bn_mean   = (const float*)d_in[9];
    const float* bn_var    = (const float*)d_in[10];
    const float* gru_wih   = (const float*)d_in[11];
    const float* gru_whh   = (const float*)d_in[12];
    const float* gru_bih   = (const float*)d_in[13];
    const float* gru_bhh   = (const float*)d_in[14];

    int Mmol = in_sizes[0] / DD;
    int n    = in_sizes[2];
    float* out = (float*)d_out;

    void* vp;
    float *p_gx, *p_gh, *p_cvec, *p_sumw;
    __half *p_pooled_h, *p_ctx_h, *p_sa_h, *p_whh_h, *p_wih_h, *p_Wa_h;
    cudaGetSymbolAddress(&vp, g_pooled_h); p_pooled_h = (__half*)vp;
    cudaGetSymbolAddress(&vp, g_ctx_h);    p_ctx_h    = (__half*)vp;
    cudaGetSymbolAddress(&vp, g_gx);       p_gx       = (float*)vp;
    cudaGetSymbolAddress(&vp, g_gh);       p_gh       = (float*)vp;
    cudaGetSymbolAddress(&vp, g_Wa_h);     p_Wa_h     = (__half*)vp;
    cudaGetSymbolAddress(&vp, g_cvec);     p_cvec     = (float*)vp;
    cudaGetSymbolAddress(&vp, g_sumw);     p_sumw     = (float*)vp;
    cudaGetSymbolAddress(&vp, g_sa_h);     p_sa_h     = (__half*)vp;
    cudaGetSymbolAddress(&vp, g_whh_h);    p_whh_h    = (__half*)vp;
    cudaGetSymbolAddress(&vp, g_wih_h);    p_wih_h    = (__half*)vp;

    if (!s_s1) {
        int prLow = 0, prHigh = 0;
        cudaDeviceGetStreamPriorityRange(&prLow, &prHigh);
        cudaStreamCreateWithPriority(&s_s1, cudaStreamNonBlocking, prLow);
        cudaStreamCreateWithFlags(&s_s2, cudaStreamNonBlocking);
        cudaEventCreateWithFlags(&s_evFork, cudaEventDisableTiming);
        cudaEventCreateWithFlags(&s_evW,    cudaEventDisableTiming);
        cudaEventCreateWithFlags(&s_evPool, cudaEventDisableTiming);
        cudaEventCreateWithFlags(&s_evJ1,   cudaEventDisableTiming);
        cudaEventCreateWithFlags(&s_evJ2,   cudaEventDisableTiming);
    }

    const int DYNSM = 2 * STAGE_H * 2;  // 40960 bytes (< 48KB default)

    int nb = (n + 255) / 256;
    dim3 g1(DD / 128, Mmol / 128);
    dim3 g2(3 * DD / 128, Mmol / 128);
    int nW = 3 * DD * DD / 8;           // tohalf threads for weight matrices
    int nS = Mmol * DD / 8;             // tohalf threads for superatom

    // ---- main (capture) stream: attention critical path ----
    k_zero_flag<<<1, 1>>>();
    cudaEventRecord(s_evFork, 0);

    // fork 1 (lowest priority): fp16 converts + whh-GEMM, overlapping pool
    cudaStreamWaitEvent(s_s1, s_evFork, 0);
    k_tohalf<<<(nS + 255) / 256, 256, 0, s_s1>>>(superatom, p_sa_h, nS);
    k_tohalf<<<(nW + 255) / 256, 256, 0, s_s1>>>(gru_whh, p_whh_h, nW);
    k_gemm_h<<<g2, 512, DYNSM, s_s1>>>(p_sa_h, p_whh_h, p_gh, nullptr, 3 * DD,
                                       gru_bhh, nullptr, 0);
    cudaEventRecord(s_evJ1, s_s1);

    // fork 2: k_weff + wih convert on s2 (needed only by the post-pool GEMMs)
    cudaStreamWaitEvent(s_s2, s_evFork, 0);
    k_weff<<<DD, 256, 0, s_s2>>>(attend_w, attend_b, bn_gamma, bn_beta, bn_mean, bn_var);
    k_tohalf<<<(nW + 255) / 256, 256, 0, s_s2>>>(gru_wih, p_wih_h, nW);
    cudaEventRecord(s_evW, s_s2);

    // main: uncontended index prep, then the DRAM-bound pool
    k_detect<<<nb, 256>>>(molidx, n);
    k_segstart<<<nb, 256>>>(molidx, n, Mmol);
    k_pool<<<(Mmol + 7) / 8, 256>>>(superatom, atom, molidx, align_w, align_b, Mmol);

    // fork 3: attention-weight output on s2 (depends only on pool + detect)
    cudaEventRecord(s_evPool, 0);
    cudaStreamWaitEvent(s_s2, s_evPool, 0);
    k_attw<<<nb, 256, 0, s_s2>>>(molidx, n, out + (size_t)Mmol * DD);
    cudaEventRecord(s_evJ2, s_s2);

    // dependent GEMM chain on main stream
    cudaStreamWaitEvent(0, s_evW, 0);
    k_gemm_h<<<g1, 512, DYNSM>>>(p_pooled_h, p_Wa_h, nullptr, p_ctx_h, DD,
                                 p_cvec, p_sumw, 1);
    k_gemm_h<<<g2, 512, DYNSM>>>(p_ctx_h, p_wih_h, p_gx, nullptr, 3 * DD,
                                 gru_bih, nullptr, 0);

    // join both branches, then the final combine
    cudaStreamWaitEvent(0, s_evJ1, 0);
    cudaStreamWaitEvent(0, s_evJ2, 0);
    k_gru<<<(Mmol * DD + 255) / 256, 256>>>(superatom, out, Mmol);
}